// round 16
// baseline (speedup 1.0000x reference)
#include <cuda_runtime.h>
#include <cuda_fp16.h>
#include <cstdint>

#define BH_  64
#define LQ_  1024
#define LK_  1024
#define DD_  64
#define TQ_  32
#define NT   256
#define KROWB  144           // K/V smem row bytes (72 fp16)
#define KBUF   18432         // one 128-row tile / one (K64,V64) pair
#define OFF_Q  36864
#define OFF_MS (OFF_Q + TQ_*KROWB)     // 41472
#define SM_TOTAL (OFF_MS + 1024)       // 42496 -> 3 CTAs/SM (regs permitting)

__device__ __half g_QH[BH_*LQ_*DD_];
__device__ __half g_KH[BH_*LK_*DD_];
__device__ __half g_VH[BH_*LK_*DD_];

__device__ __forceinline__ uint32_t s2u(const void* p) {
    uint32_t a;
    asm("{.reg .u64 t; cvta.to.shared.u64 t, %1; cvt.u32.u64 %0, t;}" : "=r"(a) : "l"(p));
    return a;
}
__device__ __forceinline__ void lm4(uint32_t* r, uint32_t addr) {
    asm volatile("ldmatrix.sync.aligned.m8n8.x4.shared.b16 {%0,%1,%2,%3}, [%4];"
                 : "=r"(r[0]), "=r"(r[1]), "=r"(r[2]), "=r"(r[3]) : "r"(addr));
}
__device__ __forceinline__ void lm4t(uint32_t* r, uint32_t addr) {
    asm volatile("ldmatrix.sync.aligned.m8n8.x4.trans.shared.b16 {%0,%1,%2,%3}, [%4];"
                 : "=r"(r[0]), "=r"(r[1]), "=r"(r[2]), "=r"(r[3]) : "r"(addr));
}
__device__ __forceinline__ void mma16816(float* c, const uint32_t* a, uint32_t b0, uint32_t b1) {
    asm volatile("mma.sync.aligned.m16n8k16.row.col.f32.f16.f16.f32 "
                 "{%0,%1,%2,%3}, {%4,%5,%6,%7}, {%8,%9}, {%0,%1,%2,%3};"
                 : "+f"(c[0]), "+f"(c[1]), "+f"(c[2]), "+f"(c[3])
                 : "r"(a[0]), "r"(a[1]), "r"(a[2]), "r"(a[3]), "r"(b0), "r"(b1));
}
__device__ __forceinline__ void cp16(char* dst, const void* src) {
    uint32_t s = s2u(dst);
    asm volatile("cp.async.cg.shared.global [%0], [%1], 16;" :: "r"(s), "l"(src));
}
__device__ __forceinline__ void cp_commit() { asm volatile("cp.async.commit_group;"); }
__device__ __forceinline__ void cp_wait0() { asm volatile("cp.async.wait_group 0;"); }
__device__ __forceinline__ void cp_wait1() { asm volatile("cp.async.wait_group 1;"); }

__device__ __forceinline__ uint32_t pack_hi2(float a, float b) {
    __half2 h = __floats2half2_rn(a, b);
    return *(uint32_t*)&h;
}

// ---------------- kernel 1: fp32 -> fp16 (single plane each) ----------------
__global__ void __launch_bounds__(256) cvt_kernel(const float* __restrict__ Q,
                                                  const float* __restrict__ K,
                                                  const float* __restrict__ V)
{
    const int which = blockIdx.y;
    const float* src = (which == 0) ? Q : (which == 1) ? K : V;
    __half* dh = (which == 0) ? g_QH : (which == 1) ? g_KH : g_VH;
    const float sc = (which == 0) ? 0.125f : 1.0f;

    size_t i = ((size_t)blockIdx.x * 256 + threadIdx.x) * 4;
    float4 f = *(const float4*)(src + i);
    f.x *= sc; f.y *= sc; f.z *= sc; f.w *= sc;
    uint2 h;
    h.x = pack_hi2(f.x, f.y); h.y = pack_hi2(f.z, f.w);
    *(uint2*)(dh + i) = h;
}

// load one 128-row fp16 tile
__device__ __forceinline__ void pf_t128(const __half* __restrict__ g, char* buf, int tid) {
    #pragma unroll
    for (int it = 0; it < 4; ++it) {
        int idx = tid + it * NT;
        int r = idx >> 3, c = idx & 7;
        cp16(buf + r * KROWB + c * 16, (const char*)(g + r * DD_) + c * 16);
    }
}
// load one (K64, V64) pair into a pass-B buffer
__device__ __forceinline__ void pf64pair(const __half* __restrict__ gk,
                                         const __half* __restrict__ gv,
                                         char* buf, int tid) {
    #pragma unroll
    for (int it = 0; it < 2; ++it) {
        int idx = tid + it * NT;
        int r = idx >> 3, c = idx & 7;
        cp16(buf + r * KROWB + c * 16,        (const char*)(gk + r * DD_) + c * 16);
        cp16(buf + 9216 + r * KROWB + c * 16, (const char*)(gv + r * DD_) + c * 16);
    }
}

// ---------------- kernel 2: two-pass fused attention (3 CTAs/SM target) ----------------
__global__ void __launch_bounds__(NT, 3)
attn_kernel(const int* __restrict__ Mg, const float* __restrict__ QMg,
            float* __restrict__ out_o, float* __restrict__ out_a)
{
    extern __shared__ char smem[];
    char* qb = smem + OFF_Q;
    float* mstat = (float*)(smem + OFF_MS);      // [32 rows][4 kg][m,s]

    const int tid  = threadIdx.x;
    const int lane = tid & 31;
    const int wid  = tid >> 5;
    const int bh   = blockIdx.y;
    const int q0   = blockIdx.x * TQ_;

    const size_t qoff = ((size_t)bh * LQ_ + q0) * DD_;
    const size_t koff = (size_t)bh * LK_ * DD_;

    const int qh2 = wid >> 2, kg = wid & 3;
    const int q0w = qh2 * 16, kb0 = kg * 16;
    const int r0   = lane >> 2;         // local fragment row 0..7
    const int colp = 2 * (lane & 3);

    // ---- prefetch Q + K tiles 0/1 (pass A uses 128-row K tiles) ----
    {
        int r = tid >> 3, c = tid & 7;
        cp16(qb + r * KROWB + c * 16, (const char*)(g_QH + qoff + r * DD_) + c * 16);
    }
    pf_t128(g_KH + koff, smem, tid);                 cp_commit();
    pf_t128(g_KH + koff + 128 * DD_, smem + KBUF, tid); cp_commit();

    const uint32_t kvu = s2u(smem);

    const int* mr0p = Mg + ((size_t)bh * LQ_ + q0 + q0w + r0) * LK_;
    const int* mr1p = mr0p + 8 * LK_;

    uint32_t aH[4][4];
    float m0 = -3.0e38f, m1 = -3.0e38f, s0 = 0.f, s1 = 0.f;
    uint32_t mb0[2] = {0u, 0u}, mb1[2] = {0u, 0u};   // mask bits, 64 per row

    // ==================== PASS A: masked online row max/sum ====================
    #pragma unroll 1
    for (int t = 0; t < 8; ++t) {
        cp_wait1();
        __syncthreads();

        if (t == 0) {
            const uint32_t uH = s2u(qb);
            const int arow = q0w + (lane & 15);
            #pragma unroll
            for (int ds = 0; ds < 4; ++ds)
                lm4(aH[ds], uH + arow * KROWB + (ds * 16 + ((lane >> 4) & 1) * 8) * 2);
        }

        const uint32_t sH = kvu + (t & 1) * KBUF;

        // mask loads (early issue)
        int2 mk0[2][2], mk1[2][2];
        #pragma unroll
        for (int h = 0; h < 2; ++h)
            #pragma unroll
            for (int j = 0; j < 2; ++j) {
                const int off = t * 128 + h * 64 + kb0 + j * 8 + colp;
                mk0[h][j] = __ldcs((const int2*)(mr0p + off));
                mk1[h][j] = __ldcs((const int2*)(mr1p + off));
            }

        float v0[8], v1[8];
        #pragma unroll
        for (int h = 0; h < 2; ++h) {
            float acc[2][4];
            #pragma unroll
            for (int j = 0; j < 2; ++j)
                #pragma unroll
                for (int e = 0; e < 4; ++e) acc[j][e] = 0.f;

            const int brow = h * 64 + kb0 + ((lane >> 4) & 1) * 8 + (lane & 7);
            #pragma unroll
            for (int ds = 0; ds < 4; ++ds) {
                uint32_t bH[4];
                lm4(bH, sH + brow * KROWB + (ds * 16 + ((lane >> 3) & 1) * 8) * 2);
                mma16816(acc[0], aH[ds], bH[0], bH[1]);
                mma16816(acc[1], aH[ds], bH[2], bH[3]);
            }
            #pragma unroll
            for (int j = 0; j < 2; ++j) {
                const int idx = t * 8 + h * 4 + j * 2;
                const uint32_t w = (uint32_t)idx >> 5, sh = (uint32_t)idx & 31;
                mb0[w] |= (((mk0[h][j].x != 0) ? 1u : 0u) | ((mk0[h][j].y != 0) ? 2u : 0u)) << sh;
                mb1[w] |= (((mk1[h][j].x != 0) ? 1u : 0u) | ((mk1[h][j].y != 0) ? 2u : 0u)) << sh;
                v0[h*4 + j*2 + 0] = (mk0[h][j].x == 0) ? -1.0e9f : acc[j][0];
                v0[h*4 + j*2 + 1] = (mk0[h][j].y == 0) ? -1.0e9f : acc[j][1];
                v1[h*4 + j*2 + 0] = (mk1[h][j].x == 0) ? -1.0e9f : acc[j][2];
                v1[h*4 + j*2 + 1] = (mk1[h][j].y == 0) ? -1.0e9f : acc[j][3];
            }
        }
        // online update
        float tm0 = v0[0], tm1 = v1[0];
        #pragma unroll
        for (int e = 1; e < 8; ++e) { tm0 = fmaxf(tm0, v0[e]); tm1 = fmaxf(tm1, v1[e]); }
        const float nm0 = fmaxf(m0, tm0), nm1 = fmaxf(m1, tm1);
        float a0 = 0.f, a1 = 0.f;
        #pragma unroll
        for (int e = 0; e < 8; ++e) { a0 += __expf(v0[e] - nm0); a1 += __expf(v1[e] - nm1); }
        s0 = s0 * __expf(m0 - nm0) + a0; m0 = nm0;
        s1 = s1 * __expf(m1 - nm1) + a1; m1 = nm1;

        __syncthreads();
        if (t + 2 < 8) {
            pf_t128(g_KH + koff + (size_t)(t + 2) * 128 * DD_, smem + (t & 1) * KBUF, tid);
        } else {
            // pass-B prologue: (K64,V64) pair T = t-6 into buffer (t&1)
            pf64pair(g_KH + koff + (size_t)(t - 6) * 64 * DD_,
                     g_VH + koff + (size_t)(t - 6) * 64 * DD_,
                     smem + (t & 1) * KBUF, tid);
        }
        cp_commit();
    }

    // ---- quad reduce (m,s) over lane&3, publish per-(row,kg), combine ----
    #pragma unroll
    for (int o = 1; o <= 2; o <<= 1) {
        float mo = __shfl_xor_sync(0xffffffffu, m0, o);
        float so = __shfl_xor_sync(0xffffffffu, s0, o);
        float nm = fmaxf(m0, mo);
        s0 = s0 * __expf(m0 - nm) + so * __expf(mo - nm); m0 = nm;
        mo = __shfl_xor_sync(0xffffffffu, m1, o);
        so = __shfl_xor_sync(0xffffffffu, s1, o);
        nm = fmaxf(m1, mo);
        s1 = s1 * __expf(m1 - nm) + so * __expf(mo - nm); m1 = nm;
    }
    if ((lane & 3) == 0) {
        mstat[((q0w + r0) * 4 + kg) * 2 + 0] = m0;
        mstat[((q0w + r0) * 4 + kg) * 2 + 1] = s0;
        mstat[((q0w + r0 + 8) * 4 + kg) * 2 + 0] = m1;
        mstat[((q0w + r0 + 8) * 4 + kg) * 2 + 1] = s1;
    }
    __syncthreads();

    float M0 = -3.0e38f, S0 = 0.f, M1 = -3.0e38f, S1 = 0.f;
    #pragma unroll
    for (int g = 0; g < 4; ++g) {
        float mg = mstat[((q0w + r0) * 4 + g) * 2 + 0];
        float sg = mstat[((q0w + r0) * 4 + g) * 2 + 1];
        float nm = fmaxf(M0, mg);
        S0 = S0 * __expf(M0 - nm) + sg * __expf(mg - nm); M0 = nm;
        mg = mstat[((q0w + r0 + 8) * 4 + g) * 2 + 0];
        sg = mstat[((q0w + r0 + 8) * 4 + g) * 2 + 1];
        nm = fmaxf(M1, mg);
        S1 = S1 * __expf(M1 - nm) + sg * __expf(mg - nm); M1 = nm;
    }
    const float scale0 = QMg[(size_t)bh * LQ_ + q0 + q0w + r0] / S0;
    const float scale1 = QMg[(size_t)bh * LQ_ + q0 + q0w + r0 + 8] / S1;

    // ==================== PASS B: recompute S, emit out_a, O += P@V ====================
    float* arow0 = out_a ? (out_a + ((size_t)bh * LQ_ + q0 + q0w + r0) * LK_) : nullptr;
    float* arow1 = out_a ? (arow0 + 8 * LK_) : nullptr;

    float oa[8][4];
    #pragma unroll
    for (int j = 0; j < 8; ++j)
        #pragma unroll
        for (int e = 0; e < 4; ++e) oa[j][e] = 0.f;

    const int vrow = kb0 + ((lane >> 3) & 1) * 8 + (lane & 7);
    const int vsub = ((lane >> 4) & 1) * 8;
    const int browB = kb0 + ((lane >> 4) & 1) * 8 + (lane & 7);

    #pragma unroll 1
    for (int t = 0; t < 16; ++t) {
        if (t == 15) cp_wait0(); else cp_wait1();
        __syncthreads();

        const uint32_t kbB = kvu + (t & 1) * KBUF;
        const uint32_t vbB = kbB + 9216;

        float acc[2][4];
        #pragma unroll
        for (int j = 0; j < 2; ++j)
            #pragma unroll
            for (int e = 0; e < 4; ++e) acc[j][e] = 0.f;

        #pragma unroll
        for (int ds = 0; ds < 4; ++ds) {
            uint32_t bH[4];
            lm4(bH, kbB + browB * KROWB + (ds * 16 + ((lane >> 3) & 1) * 8) * 2);
            mma16816(acc[0], aH[ds], bH[0], bH[1]);
            mma16816(acc[1], aH[ds], bH[2], bH[3]);
        }

        uint32_t a4[4];
        #pragma unroll
        for (int j = 0; j < 2; ++j) {
            const int idx = t * 4 + j * 2;
            const uint32_t w = (uint32_t)idx >> 5, sh = (uint32_t)idx & 31;
            const float v00 = ((mb0[w] >> sh) & 1u)       ? acc[j][0] : -1.0e9f;
            const float v01 = ((mb0[w] >> (sh + 1)) & 1u) ? acc[j][1] : -1.0e9f;
            const float v10 = ((mb1[w] >> sh) & 1u)       ? acc[j][2] : -1.0e9f;
            const float v11 = ((mb1[w] >> (sh + 1)) & 1u) ? acc[j][3] : -1.0e9f;
            const float p00 = __expf(v00 - M0) * scale0;
            const float p01 = __expf(v01 - M0) * scale0;
            const float p10 = __expf(v10 - M1) * scale1;
            const float p11 = __expf(v11 - M1) * scale1;
            if (arow0) {
                const int off = t * 64 + kb0 + j * 8 + colp;
                __stcs((float2*)(arow0 + off), make_float2(p00, p01));
                __stcs((float2*)(arow1 + off), make_float2(p10, p11));
            }
            a4[j * 2 + 0] = pack_hi2(p00, p01);
            a4[j * 2 + 1] = pack_hi2(p10, p11);
        }

        #pragma unroll
        for (int dc = 0; dc < 4; ++dc) {
            uint32_t b4[4];
            lm4t(b4, vbB + (uint32_t)vrow * KROWB + (uint32_t)(dc * 16 + vsub) * 2);
            mma16816(oa[dc * 2 + 0], a4, b4[0], b4[1]);
            mma16816(oa[dc * 2 + 1], a4, b4[2], b4[3]);
        }

        __syncthreads();
        if (t + 2 < 16) {
            pf64pair(g_KH + koff + (size_t)(t + 2) * 64 * DD_,
                     g_VH + koff + (size_t)(t + 2) * 64 * DD_,
                     smem + (t & 1) * KBUF, tid);
            cp_commit();
        }
    }

    // ---- reduce O over 4 kg warps via smem (KV region dead) ----
    float* scr = (float*)smem;              // [2 qh2][4 kg][16][68]
    const int sbase = (qh2 * 4 + kg) * 16;
    #pragma unroll
    for (int dc = 0; dc < 4; ++dc)
        #pragma unroll
        for (int nb = 0; nb < 2; ++nb) {
            const int col = dc * 16 + nb * 8 + colp;
            *(float2*)&scr[(sbase + r0) * 68 + col] =
                make_float2(oa[dc * 2 + nb][0], oa[dc * 2 + nb][1]);
            *(float2*)&scr[(sbase + r0 + 8) * 68 + col] =
                make_float2(oa[dc * 2 + nb][2], oa[dc * 2 + nb][3]);
        }
    __syncthreads();
    if (out_o) {
        const int row = tid >> 3, d8 = (tid & 7) * 8;
        const int qs = row >> 4, rl = row & 15;
        float r[8] = {0,0,0,0,0,0,0,0};
        #pragma unroll
        for (int g = 0; g < 4; ++g) {
            const float* p = &scr[((qs * 4 + g) * 16 + rl) * 68 + d8];
            #pragma unroll
            for (int e = 0; e < 8; ++e) r[e] += p[e];
        }
        float* o = out_o + ((size_t)bh * LQ_ + q0 + row) * DD_ + d8;
        *(float4*)o       = make_float4(r[0], r[1], r[2], r[3]);
        *(float4*)(o + 4) = make_float4(r[4], r[5], r[6], r[7]);
    }
}

extern "C" void kernel_launch(void* const* d_in, const int* in_sizes, int n_in,
                              void* d_out, int out_size)
{
    const float* q  = (const float*)d_in[0];
    const float* k  = (const float*)d_in[1];
    const float* v  = (const float*)d_in[2];
    const int*   m  = (const int*)d_in[3];
    const float* qm = (const float*)d_in[4];

    const long long NO = (long long)BH_ * LQ_ * DD_;
    const long long NA = (long long)BH_ * LQ_ * LK_;

    float* out_o = nullptr;
    float* out_a = nullptr;
    if ((long long)out_size >= NO + NA) {
        out_o = (float*)d_out;
        out_a = (float*)d_out + NO;
    } else if ((long long)out_size == NA) {
        out_a = (float*)d_out;
    } else {
        out_o = (float*)d_out;
    }

    cvt_kernel<<<dim3((BH_*LQ_*DD_) / (256 * 4), 3), 256>>>(q, k, v);

    cudaFuncSetAttribute(attn_kernel,
                         cudaFuncAttributeMaxDynamicSharedMemorySize, SM_TOTAL);
    attn_kernel<<<dim3(LQ_ / TQ_, BH_), NT, SM_TOTAL>>>(m, qm, out_o, out_a);
}

// round 17
// speedup vs baseline: 1.2632x; 1.2632x over previous
#include <cuda_runtime.h>
#include <cuda_fp16.h>
#include <cstdint>

#define BH_  64
#define LQ_  1024
#define LK_  1024
#define DD_  64
#define TQ_  32
#define NT   256
#define PSTR_H 2064          // S/P row bytes (1032 fp16; 129×16B -> conflict-free ldmatrix)
#define KROWB  144           // K/V smem row bytes (72 fp16)
#define KTILE  128           // K tile rows (single plane)
#define VTROWS 64            // V tile rows
#define OFF_KV (TQ_*PSTR_H)            // 66048
#define KBUFSZ (KTILE*KROWB)           // 18432 (one 128-row K tile)
#define VHALF  (VTROWS*KROWB)          // 9216  (one 64-row V tile)
#define OFF_Q  (OFF_KV + 2*KBUFSZ)     // 102912
#define QPLANE (TQ_*KROWB)             // 4608
#define SM_TOTAL (OFF_Q + QPLANE)      // 107520 -> 2 CTAs/SM

__device__ __half g_QH[BH_*LQ_*DD_];
__device__ __half g_KH[BH_*LK_*DD_];
__device__ __half g_VH[BH_*LK_*DD_];

__device__ __forceinline__ uint32_t s2u(const void* p) {
    uint32_t a;
    asm("{.reg .u64 t; cvta.to.shared.u64 t, %1; cvt.u32.u64 %0, t;}" : "=r"(a) : "l"(p));
    return a;
}
__device__ __forceinline__ void lm4(uint32_t* r, uint32_t addr) {
    asm volatile("ldmatrix.sync.aligned.m8n8.x4.shared.b16 {%0,%1,%2,%3}, [%4];"
                 : "=r"(r[0]), "=r"(r[1]), "=r"(r[2]), "=r"(r[3]) : "r"(addr));
}
__device__ __forceinline__ void lm4t(uint32_t* r, uint32_t addr) {
    asm volatile("ldmatrix.sync.aligned.m8n8.x4.trans.shared.b16 {%0,%1,%2,%3}, [%4];"
                 : "=r"(r[0]), "=r"(r[1]), "=r"(r[2]), "=r"(r[3]) : "r"(addr));
}
__device__ __forceinline__ void mma16816(float* c, const uint32_t* a, uint32_t b0, uint32_t b1) {
    asm volatile("mma.sync.aligned.m16n8k16.row.col.f32.f16.f16.f32 "
                 "{%0,%1,%2,%3}, {%4,%5,%6,%7}, {%8,%9}, {%0,%1,%2,%3};"
                 : "+f"(c[0]), "+f"(c[1]), "+f"(c[2]), "+f"(c[3])
                 : "r"(a[0]), "r"(a[1]), "r"(a[2]), "r"(a[3]), "r"(b0), "r"(b1));
}
__device__ __forceinline__ void cp16(char* dst, const void* src) {
    uint32_t s = s2u(dst);
    asm volatile("cp.async.cg.shared.global [%0], [%1], 16;" :: "r"(s), "l"(src));
}
__device__ __forceinline__ void cp_commit() { asm volatile("cp.async.commit_group;"); }
__device__ __forceinline__ void cp_wait0() { asm volatile("cp.async.wait_group 0;"); }
__device__ __forceinline__ void cp_wait1() { asm volatile("cp.async.wait_group 1;"); }

__device__ __forceinline__ uint32_t pack_hi2(float a, float b) {
    __half2 h = __floats2half2_rn(a, b);
    return *(uint32_t*)&h;
}

// ---------------- kernel 1: fp32 -> fp16 (single plane each) ----------------
__global__ void __launch_bounds__(256) cvt_kernel(const float* __restrict__ Q,
                                                  const float* __restrict__ K,
                                                  const float* __restrict__ V)
{
    const int which = blockIdx.y;
    const float* src = (which == 0) ? Q : (which == 1) ? K : V;
    __half* dh = (which == 0) ? g_QH : (which == 1) ? g_KH : g_VH;
    const float sc = (which == 0) ? 0.125f : 1.0f;

    size_t i = ((size_t)blockIdx.x * 256 + threadIdx.x) * 4;
    float4 f = *(const float4*)(src + i);
    f.x *= sc; f.y *= sc; f.z *= sc; f.w *= sc;
    uint2 h;
    h.x = pack_hi2(f.x, f.y); h.y = pack_hi2(f.z, f.w);
    *(uint2*)(dh + i) = h;
}

// load one 128-row fp16 K tile (single plane)
__device__ __forceinline__ void pf_k128(const __half* __restrict__ gh, char* buf, int tid) {
    #pragma unroll
    for (int it = 0; it < 4; ++it) {
        int idx = tid + it * NT;          // 0..1023
        int r = idx >> 3, c = idx & 7;
        cp16(buf + r * KROWB + c * 16, (const char*)(gh + r * DD_) + c * 16);
    }
}
// load one 64-row fp16 V tile (single plane)
__device__ __forceinline__ void pf_v(const __half* __restrict__ gh, char* buf, int tid) {
    #pragma unroll
    for (int it = 0; it < 2; ++it) {
        int idx = tid + it * NT;          // 0..511
        int r = idx >> 3, c = idx & 7;
        cp16(buf + r * KROWB + c * 16, (const char*)(gh + r * DD_) + c * 16);
    }
}

// ---------------- kernel 2: fused attention (2 CTAs/SM, TQ=32) ----------------
__global__ void __launch_bounds__(NT, 2)
attn_kernel(const int* __restrict__ Mg, const float* __restrict__ QMg,
            float* __restrict__ out_o, float* __restrict__ out_a)
{
    extern __shared__ char smem[];
    char* kvb   = smem + OFF_KV;
    char* qbase = smem + OFF_Q;

    const int tid  = threadIdx.x;
    const int lane = tid & 31;
    const int wid  = tid >> 5;            // 0..7
    const int bh   = blockIdx.y;
    const int q0   = blockIdx.x * TQ_;

    const size_t qoff = ((size_t)bh * LQ_ + q0) * DD_;
    const size_t koff = (size_t)bh * LK_ * DD_;

    // ---- prefetch Q (1 chunk/thread) + K tiles 0/1 ----
    {
        int r = tid >> 3, c = tid & 7;
        cp16(qbase + r * KROWB + c * 16, (const char*)(g_QH + qoff + r * DD_) + c * 16);
    }
    pf_k128(g_KH + koff, kvb, tid);
    cp_commit();
    pf_k128(g_KH + koff + KTILE * DD_, kvb + KBUFSZ, tid);
    cp_commit();

    // ===== phase 2: S = (Q/8)K^T -> Pbuf fp16; warp = 16 k-cols x ALL 32 q =====
    const int kb0 = wid * 16;             // this warp's k-columns in the 128-k tile

    uint32_t aH2[2][4][4];                // [q-half][ds][frag]

    #pragma unroll 1
    for (int t = 0; t < 8; ++t) {
        cp_wait1();
        __syncthreads();

        if (t == 0) {
            const uint32_t uH = s2u(qbase);
            #pragma unroll
            for (int h2 = 0; h2 < 2; ++h2) {
                const int arow = h2 * 16 + (lane & 15);
                #pragma unroll
                for (int ds = 0; ds < 4; ++ds) {
                    const int acol = ds * 16 + ((lane >> 4) & 1) * 8;
                    lm4(aH2[h2][ds], uH + arow * KROWB + acol * 2);
                }
            }
        }

        const uint32_t sH = s2u(kvb + (t & 1) * KBUFSZ);

        float acc[2][2][4];
        #pragma unroll
        for (int h2 = 0; h2 < 2; ++h2)
            #pragma unroll
            for (int j = 0; j < 2; ++j)
                #pragma unroll
                for (int e = 0; e < 4; ++e) acc[h2][j][e] = 0.f;

        const int brow = kb0 + ((lane >> 4) & 1) * 8 + (lane & 7);
        #pragma unroll
        for (int ds = 0; ds < 4; ++ds) {
            const int bcol = ds * 16 + ((lane >> 3) & 1) * 8;
            uint32_t bH[4];
            lm4(bH, sH + brow * KROWB + bcol * 2);
            #pragma unroll
            for (int h2 = 0; h2 < 2; ++h2) {
                mma16816(acc[h2][0], aH2[h2][ds], bH[0], bH[1]);
                mma16816(acc[h2][1], aH2[h2][ds], bH[2], bH[3]);
            }
        }

        // writeback raw S as fp16
        #pragma unroll
        for (int h2 = 0; h2 < 2; ++h2) {
            const int srow = h2 * 16 + (lane >> 2);
            char* r0 = smem + srow * PSTR_H;
            char* r1 = smem + (srow + 8) * PSTR_H;
            #pragma unroll
            for (int j = 0; j < 2; ++j) {
                const int col = t * KTILE + kb0 + j * 8 + 2 * (lane & 3);
                *(uint32_t*)(r0 + col * 2) = pack_hi2(acc[h2][j][0], acc[h2][j][1]);
                *(uint32_t*)(r1 + col * 2) = pack_hi2(acc[h2][j][2], acc[h2][j][3]);
            }
        }

        __syncthreads();
        if (t + 2 < 8) {
            pf_k128(g_KH + koff + (size_t)(t + 2) * KTILE * DD_, kvb + (t & 1) * KBUFSZ, tid);
        } else {
            // V0 -> kvb (t=6), V1 -> kvb+KBUFSZ (t=7)
            pf_v(g_VH + koff + (size_t)(t - 6) * VTROWS * DD_, kvb + (t & 1) * KBUFSZ, tid);
        }
        cp_commit();
    }

    // ================ phase 3: mask + softmax; p back as fp16 + out_a fp32 ================
    #pragma unroll 1
    for (int i = 0; i < 4; ++i) {
        const int q = wid * 4 + i;
        char* rowb = smem + q * PSTR_H;
        const int4* mrow = (const int4*)(Mg + ((size_t)bh * LQ_ + q0 + q) * LK_);

        float v[32];
        float mx = -3.0e38f;
        #pragma unroll
        for (int c = 0; c < 4; ++c) {
            const int idx = c * 32 + lane;
            uint4 sv = *(uint4*)(rowb + idx * 16);
            int4 ma = mrow[idx * 2], mb = mrow[idx * 2 + 1];
            float2 f0 = __half22float2(*(__half2*)&sv.x);
            float2 f1 = __half22float2(*(__half2*)&sv.y);
            float2 f2 = __half22float2(*(__half2*)&sv.z);
            float2 f3 = __half22float2(*(__half2*)&sv.w);
            float* vv = v + c * 8;
            vv[0] = (ma.x == 0) ? -1.0e9f : f0.x;
            vv[1] = (ma.y == 0) ? -1.0e9f : f0.y;
            vv[2] = (ma.z == 0) ? -1.0e9f : f1.x;
            vv[3] = (ma.w == 0) ? -1.0e9f : f1.y;
            vv[4] = (mb.x == 0) ? -1.0e9f : f2.x;
            vv[5] = (mb.y == 0) ? -1.0e9f : f2.y;
            vv[6] = (mb.z == 0) ? -1.0e9f : f3.x;
            vv[7] = (mb.w == 0) ? -1.0e9f : f3.y;
            #pragma unroll
            for (int e = 0; e < 8; ++e) mx = fmaxf(mx, vv[e]);
        }
        #pragma unroll
        for (int o = 16; o > 0; o >>= 1)
            mx = fmaxf(mx, __shfl_xor_sync(0xffffffffu, mx, o));

        float sum = 0.f;
        #pragma unroll
        for (int e = 0; e < 32; ++e) { v[e] = __expf(v[e] - mx); sum += v[e]; }
        #pragma unroll
        for (int o = 16; o > 0; o >>= 1)
            sum += __shfl_xor_sync(0xffffffffu, sum, o);

        const float sc = QMg[(size_t)bh * LQ_ + q0 + q] / sum;
        float* arow = out_a ? (out_a + ((size_t)bh * LQ_ + q0 + q) * LK_) : nullptr;
        #pragma unroll
        for (int c = 0; c < 4; ++c) {
            const int idx = c * 32 + lane;
            float* vv = v + c * 8;
            #pragma unroll
            for (int e = 0; e < 8; ++e) vv[e] *= sc;
            if (arow) {
                __stcs((float4*)(arow + idx * 8),     make_float4(vv[0], vv[1], vv[2], vv[3]));
                __stcs((float4*)(arow + idx * 8 + 4), make_float4(vv[4], vv[5], vv[6], vv[7]));
            }
            uint4 pk;
            pk.x = pack_hi2(vv[0], vv[1]); pk.y = pack_hi2(vv[2], vv[3]);
            pk.z = pack_hi2(vv[4], vv[5]); pk.w = pack_hi2(vv[6], vv[7]);
            *(uint4*)(rowb + idx * 16) = pk;
        }
    }

    // ================ phase 4: O = P @ V — warp = (qh4, nh n32, kh k-split) ================
    const int qh4 = wid >> 2;            // 0..1
    const int nh  = (wid >> 1) & 1;      // 0..1
    const int kh  = wid & 1;             // 0..1
    const int q0o = qh4 * 16, n0 = nh * 32;
    const uint32_t pbase = s2u(smem);

    float oa[4][4];
    #pragma unroll
    for (int j = 0; j < 4; ++j)
        #pragma unroll
        for (int e = 0; e < 4; ++e) oa[j][e] = 0.f;

    const int arow = q0o + (lane & 15);
    const int vrl  = ((lane >> 3) & 1) * 8 + (lane & 7);
    const int vsub = ((lane >> 4) & 1) * 8;

    #pragma unroll 1
    for (int t = 0; t < 16; ++t) {
        if (t == 15) cp_wait0(); else cp_wait1();
        __syncthreads();                 // t==0 also publishes phase-3 p planes

        const uint32_t vH = s2u(kvb + (t & 1) * KBUFSZ);

        #pragma unroll
        for (int ks = 0; ks < 2; ++ks) {
            const int k0 = kh * 32 + ks * 16;
            uint32_t a4[4];
            const uint32_t ab = pbase + arow * PSTR_H +
                                2 * (t * VTROWS + k0 + ((lane >> 4) & 1) * 8);
            lm4(a4, ab);

            const uint32_t vrow = (uint32_t)(k0 + vrl) * KROWB;
            #pragma unroll
            for (int nb2 = 0; nb2 < 2; ++nb2) {
                uint32_t b4[4];
                lm4t(b4, vH + vrow + (uint32_t)(n0 + nb2 * 16 + vsub) * 2);
                mma16816(oa[nb2 * 2 + 0], a4, b4[0], b4[1]);
                mma16816(oa[nb2 * 2 + 1], a4, b4[2], b4[3]);
            }
        }

        __syncthreads();
        if (t + 2 < 16) {
            pf_v(g_VH + koff + (size_t)(t + 2) * VTROWS * DD_, kvb + (t & 1) * KBUFSZ, tid);
            cp_commit();
        }
    }

    // ---- kh reduction via scratch (dead region: V tiles use only first 9216 of each slot) ----
    float* scr = (float*)(kvb + VHALF);    // [4 grp][16][34] floats = 8704 B < 9216
    const int grp = qh4 * 2 + nh;
    __syncthreads();
    if (kh == 1) {
        #pragma unroll
        for (int j = 0; j < 4; ++j) {
            const int cl = j * 8 + 2 * (lane & 3);
            float* s0 = scr + grp * (16 * 34) + (lane >> 2) * 34 + cl;
            *(float2*)s0 = make_float2(oa[j][0], oa[j][1]);
            *(float2*)(s0 + 8 * 34) = make_float2(oa[j][2], oa[j][3]);
        }
    }
    __syncthreads();
    if (kh == 0 && out_o) {
        const int row0 = q0 + q0o + (lane >> 2);
        #pragma unroll
        for (int j = 0; j < 4; ++j) {
            const int cl = j * 8 + 2 * (lane & 3);
            float2 s0 = *(float2*)(scr + grp * (16 * 34) + (lane >> 2) * 34 + cl);
            float2 s1 = *(float2*)(scr + grp * (16 * 34) + ((lane >> 2) + 8) * 34 + cl);
            float* o0 = out_o + ((size_t)bh * LQ_ + row0) * DD_ + n0 + cl;
            *(float2*)o0 = make_float2(oa[j][0] + s0.x, oa[j][1] + s0.y);
            *(float2*)(o0 + 8 * DD_) = make_float2(oa[j][2] + s1.x, oa[j][3] + s1.y);
        }
    }
}

extern "C" void kernel_launch(void* const* d_in, const int* in_sizes, int n_in,
                              void* d_out, int out_size)
{
    const float* q  = (const float*)d_in[0];
    const float* k  = (const float*)d_in[1];
    const float* v  = (const float*)d_in[2];
    const int*   m  = (const int*)d_in[3];
    const float* qm = (const float*)d_in[4];

    const long long NO = (long long)BH_ * LQ_ * DD_;
    const long long NA = (long long)BH_ * LQ_ * LK_;

    float* out_o = nullptr;
    float* out_a = nullptr;
    if ((long long)out_size >= NO + NA) {
        out_o = (float*)d_out;
        out_a = (float*)d_out + NO;
    } else if ((long long)out_size == NA) {
        out_a = (float*)d_out;
    } else {
        out_o = (float*)d_out;
    }

    cvt_kernel<<<dim3((BH_*LQ_*DD_) / (256 * 4), 3), 256>>>(q, k, v);

    cudaFuncSetAttribute(attn_kernel,
                         cudaFuncAttributeMaxDynamicSharedMemorySize, SM_TOTAL);
    attn_kernel<<<dim3(LQ_ / TQ_, BH_), NT, SM_TOTAL>>>(m, qm, out_o, out_a);
}